// round 7
// baseline (speedup 1.0000x reference)
#include <cuda_runtime.h>
#include <cstdint>
#include <math.h>

// ---------------------------------------------------------------------------
// Problem constants
// ---------------------------------------------------------------------------
#define BSZ   8192
#define DIN   2048
#define H0D   1024
#define H1D   512
#define LATD  128
#define NC    8

// ---------------------------------------------------------------------------
// Scratch (device globals)
// ---------------------------------------------------------------------------
// activations int8 (2-level) + scales
__device__ int8_t g_xq1[(size_t)BSZ * DIN];
__device__ int8_t g_xq2[(size_t)BSZ * DIN];
__device__ float  g_sx [BSZ];
__device__ int8_t g_aq1[(size_t)BSZ * H0D];   // h0, later d1
__device__ int8_t g_aq2[(size_t)BSZ * H0D];
__device__ float  g_sa [BSZ];
__device__ int8_t g_dq1[(size_t)BSZ * H1D];   // d0
__device__ int8_t g_dq2[(size_t)BSZ * H1D];
__device__ float  g_sd [BSZ];
// weights int8 [N,K] (transposed) + per-row scales
__device__ int8_t g_w0q1[(size_t)NC * H0D * DIN];
__device__ int8_t g_w0q2[(size_t)NC * H0D * DIN];
__device__ float  g_sw0 [NC * H0D];
__device__ int8_t g_w1q1[(size_t)H1D * H0D];
__device__ int8_t g_w1q2[(size_t)H1D * H0D];
__device__ float  g_sw1 [H1D];
__device__ int8_t g_wd1q1[(size_t)NC * H0D * H1D];
__device__ int8_t g_wd1q2[(size_t)NC * H0D * H1D];
__device__ float  g_swd1 [NC * H0D];
__device__ int8_t g_woq1[(size_t)DIN * H0D];
__device__ int8_t g_woq2[(size_t)DIN * H0D];
__device__ float  g_swo [DIN];
// fp32 scratch
__device__ float g_h0f[(size_t)BSZ * H0D];    // h0, later d1
__device__ float g_h1 [(size_t)BSZ * H1D];    // h1, later d0
__device__ float g_z  [(size_t)BSZ * LATD];
__device__ int   g_perm[NC * BSZ];
__device__ int   g_counts[NC];

// ---------------------------------------------------------------------------
// Routing
// ---------------------------------------------------------------------------
__global__ void reset_counts_k() {
    if (threadIdx.x < NC) g_counts[threadIdx.x] = 0;
}
__global__ void scatter_k(const int* __restrict__ labels) {
    int b = blockIdx.x * blockDim.x + threadIdx.x;
    if (b < BSZ) {
        int c = labels[b];
        int p = atomicAdd(&g_counts[c], 1);
        g_perm[c * BSZ + p] = b;
    }
}

// ---------------------------------------------------------------------------
// Row quantize: per-row scale s = max|v|/127; q1 = rn(v/s); q2 = rn(254*(v/s-q1))
// One block (256 thr) per row.
// ---------------------------------------------------------------------------
__global__ void rowquant_k(const float* __restrict__ X,
                           int8_t* __restrict__ Q1, int8_t* __restrict__ Q2,
                           float* __restrict__ S, int K) {
    int row = blockIdx.x;
    int t = threadIdx.x;
    const float4* xr = reinterpret_cast<const float4*>(X + (size_t)row * K);
    int n4 = K / 4;
    float m = 0.f;
    for (int i = t; i < n4; i += 256) {
        float4 v = xr[i];
        m = fmaxf(m, fmaxf(fmaxf(fabsf(v.x), fabsf(v.y)),
                           fmaxf(fabsf(v.z), fabsf(v.w))));
    }
    __shared__ float red[256];
    red[t] = m; __syncthreads();
    for (int s = 128; s > 0; s >>= 1) {
        if (t < s) red[t] = fmaxf(red[t], red[t + s]);
        __syncthreads();
    }
    float mx = red[0];
    float inv = (mx > 0.f) ? 127.f / mx : 0.f;
    if (t == 0) S[row] = mx / 127.f;
    uint32_t* q1w = reinterpret_cast<uint32_t*>(Q1 + (size_t)row * K);
    uint32_t* q2w = reinterpret_cast<uint32_t*>(Q2 + (size_t)row * K);
    for (int i = t; i < n4; i += 256) {
        float4 v = xr[i];
        float vv[4] = {v.x, v.y, v.z, v.w};
        uint32_t p1 = 0, p2 = 0;
        #pragma unroll
        for (int j = 0; j < 4; j++) {
            float u = vv[j] * inv;
            int q1 = __float2int_rn(u);
            int q2 = __float2int_rn((u - (float)q1) * 254.f);
            p1 |= (uint32_t)(q1 & 0xff) << (8 * j);
            p2 |= (uint32_t)(q2 & 0xff) << (8 * j);
        }
        q1w[i] = p1;
        q2w[i] = p2;
    }
}

// ---------------------------------------------------------------------------
// Weight column max (per output neuron n): W [K,N] fp32, grid.z = group
// ---------------------------------------------------------------------------
__global__ void wcolmax_k(const float* __restrict__ W, float* __restrict__ SB,
                          int K, int N) {
    int g = blockIdx.z;
    int n = blockIdx.x * 256 + threadIdx.x;
    if (n >= N) return;
    const float* base = W + (size_t)g * K * N + n;
    float m = 0.f;
    for (int k = 0; k < K; k++)
        m = fmaxf(m, fabsf(base[(size_t)k * N]));
    SB[g * N + n] = m / 127.f;
}

// Weight quantize + transpose: W [K,N] fp32 -> Q1/Q2 [N,K] int8. grid.z = group.
__global__ void wquant_k(const float* __restrict__ W, const float* __restrict__ SB,
                         int8_t* __restrict__ Q1, int8_t* __restrict__ Q2,
                         int K, int N) {
    __shared__ float tile[32][33];
    int g = blockIdx.z;
    const float* Wg = W + (size_t)g * K * N;
    int8_t* Q1g = Q1 + (size_t)g * N * K;
    int8_t* Q2g = Q2 + (size_t)g * N * K;
    int n0 = blockIdx.x * 32, k0 = blockIdx.y * 32;
    int tx = threadIdx.x, ty = threadIdx.y;   // 32 x 8
    #pragma unroll
    for (int i = 0; i < 4; i++)
        tile[ty + 8 * i][tx] = Wg[(size_t)(k0 + ty + 8 * i) * N + n0 + tx];
    __syncthreads();
    #pragma unroll
    for (int i = 0; i < 4; i++) {
        int n = n0 + ty + 8 * i;
        float sb = SB[g * N + n];
        float inv = (sb > 0.f) ? 1.f / sb : 0.f;
        float u = tile[tx][ty + 8 * i] * inv;
        int q1 = __float2int_rn(u);
        int q2 = __float2int_rn((u - (float)q1) * 254.f);
        size_t o = (size_t)n * K + k0 + tx;
        Q1g[o] = (int8_t)q1;
        Q2g[o] = (int8_t)q2;
    }
}

// ---------------------------------------------------------------------------
// PTX wrappers
// ---------------------------------------------------------------------------
__device__ __forceinline__ uint32_t smem_u32(const void* p) {
    uint32_t a;
    asm("{ .reg .u64 t; cvta.to.shared.u64 t, %1; cvt.u32.u64 %0, t; }"
        : "=r"(a) : "l"(p));
    return a;
}

__device__ __forceinline__ void cp_async16(uint32_t saddr, const void* g, bool ok) {
    int sz = ok ? 16 : 0;
    asm volatile("cp.async.cg.shared.global [%0], [%1], 16, %2;"
                 :: "r"(saddr), "l"(g), "r"(sz));
}
#define CP_COMMIT() asm volatile("cp.async.commit_group;" ::: "memory")
#define CP_WAIT(n)  asm volatile("cp.async.wait_group %0;" :: "n"(n) : "memory")

__device__ __forceinline__ void ldsm_x4(uint32_t* r, uint32_t addr) {
    asm volatile("ldmatrix.sync.aligned.m8n8.x4.shared.b16 {%0,%1,%2,%3}, [%4];"
                 : "=r"(r[0]), "=r"(r[1]), "=r"(r[2]), "=r"(r[3]) : "r"(addr));
}

__device__ __forceinline__ void mma_s8(int* c, const uint32_t* a, const uint32_t* b) {
    asm volatile(
        "mma.sync.aligned.m16n8k32.row.col.s32.s8.s8.s32 "
        "{%0,%1,%2,%3}, {%4,%5,%6,%7}, {%8,%9}, {%0,%1,%2,%3};"
        : "+r"(c[0]), "+r"(c[1]), "+r"(c[2]), "+r"(c[3])
        : "r"(a[0]), "r"(a[1]), "r"(a[2]), "r"(a[3]), "r"(b[0]), "r"(b[1]));
}

// ---------------------------------------------------------------------------
// int8 tensor-core GEMM: 128x128 CTA tile, K-chunk 64 (int8 bytes), 512 thr,
// warp grid 4x4 (warp tile 32x32), 4-stage cp.async pipeline.
// smem rows: 64 int8 = 64B tight; XOR chunk swizzle c' = v ^ ((row>>1)&3).
// C = s_a[m] * s_b[n] * (Q11 + (Q12 + Q21)/254) + bias[n]
// ---------------------------------------------------------------------------
#define S8_BM 128
#define S8_BN 128
#define S8_KC 64
#define S8_THREADS 512
#define S8_NSTAGE 4
#define S8_TILE 8192                       // 128 rows * 64 B, per level
#define S8_STAGE (4 * S8_TILE)             // A1 A2 B1 B2 = 32 KB
#define S8_ROWS_OFF (S8_NSTAGE * S8_STAGE) // 131072
#define S8_SMEM_TOTAL (S8_ROWS_OFF + S8_BM * 4)

__device__ __forceinline__ uint32_t swz(int row, int v) {
    return (uint32_t)(row * 64 + ((v ^ ((row >> 1) & 3)) << 4));
}

template <bool GROUPED>
__device__ __forceinline__ void s8_load_stage(
    uint32_t sb, const int* __restrict__ rows, int tid, int stage, int k0,
    const int8_t* __restrict__ A1, const int8_t* __restrict__ A2,
    const int8_t* __restrict__ B1, const int8_t* __restrict__ B2,
    int m0, int n0, int K)
{
    uint32_t base = sb + stage * S8_STAGE;
    #pragma unroll
    for (int t = 0; t < 4; t++) {
        int idx = tid + t * S8_THREADS;     // 0..2047
        if (idx < 1024) {
            int lvl = idx >> 9;
            int rem = idx & 511;
            int row = rem >> 2;
            int v   = rem & 3;
            int gr = GROUPED ? rows[row] : (m0 + row);
            bool ok = !GROUPED || (gr >= 0);
            const int8_t* src = lvl ? A2 : A1;
            cp_async16(base + lvl * S8_TILE + swz(row, v),
                       src + (size_t)(ok ? gr : 0) * K + k0 + v * 16, ok);
        } else {
            int j   = idx - 1024;
            int lvl = j >> 9;
            int rem = j & 511;
            int row = rem >> 2;
            int v   = rem & 3;
            const int8_t* src = lvl ? B2 : B1;
            cp_async16(base + 2 * S8_TILE + lvl * S8_TILE + swz(row, v),
                       src + (size_t)(n0 + row) * K + k0 + v * 16, true);
        }
    }
}

template <bool RELU, bool GROUPED>
__global__ void __launch_bounds__(S8_THREADS, 1)
tc_s8_k(const int8_t* __restrict__ Aq1, const int8_t* __restrict__ Aq2,
        const float* __restrict__ SA,
        const int8_t* __restrict__ Bq1g, const int8_t* __restrict__ Bq2g,
        const float* __restrict__ SBg,
        const float* __restrict__ biasg, float* __restrict__ OutF,
        int M, int N, int K)
{
    extern __shared__ char smem[];
    const int tid  = threadIdx.x;
    const int wid  = tid >> 5;
    const int lane = tid & 31;
    const int wm   = wid >> 2;   // 0..3 (32-row band)
    const int wn   = wid & 3;    // 0..3 (32-col band)
    const int g    = GROUPED ? blockIdx.z : 0;
    const int m0   = blockIdx.y * S8_BM;
    if (GROUPED) {
        if (m0 >= g_counts[g]) return;
    }
    const int n0 = blockIdx.x * S8_BN;
    uint32_t sb = smem_u32(smem);
    int* rows_s = reinterpret_cast<int*>(smem + S8_ROWS_OFF);

    if (GROUPED) {
        if (tid < S8_BM) {
            int cnt = g_counts[g];
            int r = m0 + tid;
            rows_s[tid] = (r < cnt) ? g_perm[g * BSZ + r] : -1;
        }
        __syncthreads();
    }

    const int8_t* B1 = Bq1g + (GROUPED ? (size_t)g * N * K : 0);
    const int8_t* B2 = Bq2g + (GROUPED ? (size_t)g * N * K : 0);

    int acc1[2][4][4], acc2[2][4][4];
    #pragma unroll
    for (int i = 0; i < 2; i++)
        #pragma unroll
        for (int j = 0; j < 4; j++)
            #pragma unroll
            for (int q = 0; q < 4; q++) { acc1[i][j][q] = 0; acc2[i][j][q] = 0; }

    const int nchunks = K / S8_KC;

    // prologue: up to 3 stages
    #pragma unroll
    for (int p = 0; p < S8_NSTAGE - 1; p++) {
        if (p < nchunks) {
            s8_load_stage<GROUPED>(sb, rows_s, tid, p, p * S8_KC,
                                   Aq1, Aq2, B1, B2, m0, n0, K);
            CP_COMMIT();
        }
    }

    int stage = 0;
    for (int i = 0; i < nchunks; i++) {
        if      (i + 3 <= nchunks - 1) { CP_WAIT(2); }
        else if (i + 2 <= nchunks - 1) { CP_WAIT(1); }
        else                           { CP_WAIT(0); }
        __syncthreads();

        if (i + S8_NSTAGE - 1 < nchunks) {
            int ps = stage + S8_NSTAGE - 1; if (ps >= S8_NSTAGE) ps -= S8_NSTAGE;
            s8_load_stage<GROUPED>(sb, rows_s, tid, ps, (i + S8_NSTAGE - 1) * S8_KC,
                                   Aq1, Aq2, B1, B2, m0, n0, K);
            CP_COMMIT();
        }

        uint32_t st = sb + stage * S8_STAGE;
        #pragma unroll
        for (int kk = 0; kk < 2; kk++) {
            const int vb = kk * 2 + (lane >> 4);
            uint32_t b1f[8], b2f[8];
            #pragma unroll
            for (int p = 0; p < 2; p++) {
                int brow = wn * 32 + p * 16 + (lane & 15);
                uint32_t r[4];
                ldsm_x4(r, st + 2 * S8_TILE + swz(brow, vb));
                b1f[4 * p + 0] = r[0]; b1f[4 * p + 1] = r[2];
                b1f[4 * p + 2] = r[1]; b1f[4 * p + 3] = r[3];
                ldsm_x4(r, st + 3 * S8_TILE + swz(brow, vb));
                b2f[4 * p + 0] = r[0]; b2f[4 * p + 1] = r[2];
                b2f[4 * p + 2] = r[1]; b2f[4 * p + 3] = r[3];
            }
            uint32_t a[2][4];
            #pragma unroll
            for (int mt = 0; mt < 2; mt++) {
                int arow = wm * 32 + mt * 16 + (lane & 15);
                ldsm_x4(a[mt], st + swz(arow, vb));
            }
            #pragma unroll
            for (int mt = 0; mt < 2; mt++)
                #pragma unroll
                for (int nt = 0; nt < 4; nt++) {
                    mma_s8(acc1[mt][nt], a[mt], &b1f[2 * nt]);
                    mma_s8(acc2[mt][nt], a[mt], &b2f[2 * nt]);
                }
            #pragma unroll
            for (int mt = 0; mt < 2; mt++) {
                int arow = wm * 32 + mt * 16 + (lane & 15);
                ldsm_x4(a[mt], st + S8_TILE + swz(arow, vb));
            }
            #pragma unroll
            for (int mt = 0; mt < 2; mt++)
                #pragma unroll
                for (int nt = 0; nt < 4; nt++)
                    mma_s8(acc2[mt][nt], a[mt], &b1f[2 * nt]);
        }
        stage = stage + 1; if (stage >= S8_NSTAGE) stage = 0;
    }

    // Epilogue: C = sa*sb*(acc1 + acc2/254) + bias
    const float INV254 = 1.f / 254.f;
    const float* bias = biasg + (GROUPED ? (size_t)g * N : 0);
    const float* SB = SBg + (GROUPED ? (size_t)g * N : 0);
    #pragma unroll
    for (int mt = 0; mt < 2; mt++) {
        #pragma unroll
        for (int half = 0; half < 2; half++) {
            int rloc = wm * 32 + mt * 16 + (lane >> 2) + half * 8;
            int gm = GROUPED ? rows_s[rloc] : (m0 + rloc);
            if (GROUPED && gm < 0) continue;
            float sa = SA[gm];
            #pragma unroll
            for (int nt = 0; nt < 4; nt++) {
                int col = n0 + wn * 32 + nt * 8 + 2 * (lane & 3);
                float s0 = sa * SB[col];
                float s1 = sa * SB[col + 1];
                float c0 = s0 * ((float)acc1[mt][nt][2 * half + 0]
                                 + (float)acc2[mt][nt][2 * half + 0] * INV254)
                           + bias[col];
                float c1 = s1 * ((float)acc1[mt][nt][2 * half + 1]
                                 + (float)acc2[mt][nt][2 * half + 1] * INV254)
                           + bias[col + 1];
                if (RELU) { c0 = fmaxf(c0, 0.f); c1 = fmaxf(c1, 0.f); }
                *reinterpret_cast<float2*>(OutF + (size_t)gm * N + col) =
                    make_float2(c0, c1);
            }
        }
    }
}

// ---------------------------------------------------------------------------
// SIMT fp32 GEMM (small layers)
// ---------------------------------------------------------------------------
#define BM 128
#define BN 128
#define BK 16
#define TM 8
#define TN 8
#define NTHREADS 256

template <bool RELU>
__global__ __launch_bounds__(NTHREADS)
void gemm_k(const float* __restrict__ A, const float* __restrict__ W,
            const float* __restrict__ bias, float* __restrict__ Out,
            int N, int K) {
    __shared__ float As[BK][BM];
    __shared__ float Bs[BK][BN];

    const int tid = threadIdx.x;
    const int tx = tid & 15;
    const int ty = tid >> 4;
    const int m0 = blockIdx.y * BM;
    const int n0 = blockIdx.x * BN;

    const float* Aptr = A + (size_t)m0 * K;
    const float* Wptr = W + n0;

    float acc[TM][TN];
    #pragma unroll
    for (int i = 0; i < TM; i++)
        #pragma unroll
        for (int j = 0; j < TN; j++) acc[i][j] = 0.f;

    for (int k0 = 0; k0 < K; k0 += BK) {
        #pragma unroll
        for (int i = 0; i < 2; i++) {
            int idx = tid + i * NTHREADS;
            int row = idx >> 2;
            int c4  = idx & 3;
            float4 v = *reinterpret_cast<const float4*>(Aptr + (size_t)row * K + k0 + c4 * 4);
            As[c4 * 4 + 0][row] = v.x;
            As[c4 * 4 + 1][row] = v.y;
            As[c4 * 4 + 2][row] = v.z;
            As[c4 * 4 + 3][row] = v.w;
        }
        #pragma unroll
        for (int i = 0; i < 2; i++) {
            int idx = tid + i * NTHREADS;
            int row = idx >> 5;
            int c4  = idx & 31;
            float4 v = *reinterpret_cast<const float4*>(Wptr + (size_t)(k0 + row) * N + c4 * 4);
            *reinterpret_cast<float4*>(&Bs[row][c4 * 4]) = v;
        }
        __syncthreads();

        #pragma unroll
        for (int k = 0; k < BK; k++) {
            float ra[TM], rb[TN];
            #pragma unroll
            for (int i = 0; i < TM; i++) ra[i] = As[k][ty * TM + i];
            #pragma unroll
            for (int j = 0; j < TN; j++) rb[j] = Bs[k][tx * TN + j];
            #pragma unroll
            for (int i = 0; i < TM; i++)
                #pragma unroll
                for (int j = 0; j < TN; j++)
                    acc[i][j] = fmaf(ra[i], rb[j], acc[i][j]);
        }
        __syncthreads();
    }

    #pragma unroll
    for (int i = 0; i < TM; i++) {
        int m = m0 + ty * TM + i;
        size_t obase = (size_t)m * N + n0 + tx * TN;
        #pragma unroll
        for (int j4 = 0; j4 < 2; j4++) {
            float4 v;
            float* a = &acc[i][j4 * 4];
            const float* bp = bias + n0 + tx * TN + j4 * 4;
            v.x = a[0] + bp[0]; v.y = a[1] + bp[1];
            v.z = a[2] + bp[2]; v.w = a[3] + bp[3];
            if (RELU) {
                v.x = fmaxf(v.x, 0.f); v.y = fmaxf(v.y, 0.f);
                v.z = fmaxf(v.z, 0.f); v.w = fmaxf(v.w, 0.f);
            }
            *reinterpret_cast<float4*>(Out + obase + j4 * 4) = v;
        }
    }
}

// ---------------------------------------------------------------------------
// Reparameterize
// ---------------------------------------------------------------------------
__global__ void z_k(const float* __restrict__ mu, const float* __restrict__ logvar,
                    const float* __restrict__ eps, float* __restrict__ z, int n) {
    int i = blockIdx.x * blockDim.x + threadIdx.x;
    if (i < n) z[i] = fmaf(eps[i], expf(0.5f * logvar[i]), mu[i]);
}

// ---------------------------------------------------------------------------
// Launcher
// ---------------------------------------------------------------------------
extern "C" void kernel_launch(void* const* d_in, const int* in_sizes, int n_in,
                              void* d_out, int out_size) {
    const float* x        = (const float*)d_in[0];
    const int*   labels   = (const int*)  d_in[1];
    const float* eps      = (const float*)d_in[2];
    const float* W_enc0   = (const float*)d_in[3];
    const float* b_enc0   = (const float*)d_in[4];
    const float* W_enc1   = (const float*)d_in[5];
    const float* b_enc1   = (const float*)d_in[6];
    const float* W_mu     = (const float*)d_in[7];
    const float* b_mu     = (const float*)d_in[8];
    const float* W_logvar = (const float*)d_in[9];
    const float* b_logvar = (const float*)d_in[10];
    const float* W_dec0   = (const float*)d_in[11];
    const float* b_dec0   = (const float*)d_in[12];
    const float* W_dec1   = (const float*)d_in[13];
    const float* b_dec1   = (const float*)d_in[14];
    const float* W_out    = (const float*)d_in[15];
    const float* b_out    = (const float*)d_in[16];

    float* recon  = (float*)d_out;
    float* mu     = recon + (size_t)BSZ * DIN;
    float* logvar = mu    + (size_t)BSZ * LATD;

    int8_t *xq1, *xq2, *aq1, *aq2, *dq1, *dq2;
    int8_t *w0q1, *w0q2, *w1q1, *w1q2, *wd1q1, *wd1q2, *woq1, *woq2;
    float *sx, *sa, *sd, *sw0, *sw1, *swd1, *swo, *h0f, *h1p, *zp;
    cudaGetSymbolAddress((void**)&xq1, g_xq1);  cudaGetSymbolAddress((void**)&xq2, g_xq2);
    cudaGetSymbolAddress((void**)&aq1, g_aq1);  cudaGetSymbolAddress((void**)&aq2, g_aq2);
    cudaGetSymbolAddress((void**)&dq1, g_dq1);  cudaGetSymbolAddress((void**)&dq2, g_dq2);
    cudaGetSymbolAddress((void**)&sx,  g_sx);   cudaGetSymbolAddress((void**)&sa,  g_sa);
    cudaGetSymbolAddress((void**)&sd,  g_sd);
    cudaGetSymbolAddress((void**)&w0q1, g_w0q1); cudaGetSymbolAddress((void**)&w0q2, g_w0q2);
    cudaGetSymbolAddress((void**)&w1q1, g_w1q1); cudaGetSymbolAddress((void**)&w1q2, g_w1q2);
    cudaGetSymbolAddress((void**)&wd1q1, g_wd1q1); cudaGetSymbolAddress((void**)&wd1q2, g_wd1q2);
    cudaGetSymbolAddress((void**)&woq1, g_woq1); cudaGetSymbolAddress((void**)&woq2, g_woq2);
    cudaGetSymbolAddress((void**)&sw0, g_sw0);  cudaGetSymbolAddress((void**)&sw1, g_sw1);
    cudaGetSymbolAddress((void**)&swd1, g_swd1); cudaGetSymbolAddress((void**)&swo, g_swo);
    cudaGetSymbolAddress((void**)&h0f, g_h0f);  cudaGetSymbolAddress((void**)&h1p, g_h1);
    cudaGetSymbolAddress((void**)&zp,  g_z);

    cudaFuncSetAttribute(tc_s8_k<true,  true>,
                         cudaFuncAttributeMaxDynamicSharedMemorySize, S8_SMEM_TOTAL);
    cudaFuncSetAttribute(tc_s8_k<true,  false>,
                         cudaFuncAttributeMaxDynamicSharedMemorySize, S8_SMEM_TOTAL);
    cudaFuncSetAttribute(tc_s8_k<false, false>,
                         cudaFuncAttributeMaxDynamicSharedMemorySize, S8_SMEM_TOTAL);

    // 1. routing
    reset_counts_k<<<1, 32>>>();
    scatter_k<<<BSZ / 256, 256>>>(labels);

    // 2. quantize input + weights
    rowquant_k<<<BSZ, 256>>>(x, xq1, xq2, sx, DIN);
    wcolmax_k<<<dim3(H0D / 256, 1, NC), 256>>>(W_enc0, sw0, DIN, H0D);
    wquant_k<<<dim3(H0D / 32, DIN / 32, NC), dim3(32, 8)>>>(W_enc0, sw0, w0q1, w0q2, DIN, H0D);
    wcolmax_k<<<dim3(H1D / 256, 1, 1), 256>>>(W_enc1, sw1, H0D, H1D);
    wquant_k<<<dim3(H1D / 32, H0D / 32, 1), dim3(32, 8)>>>(W_enc1, sw1, w1q1, w1q2, H0D, H1D);
    wcolmax_k<<<dim3(H0D / 256, 1, NC), 256>>>(W_dec1, swd1, H1D, H0D);
    wquant_k<<<dim3(H0D / 32, H1D / 32, NC), dim3(32, 8)>>>(W_dec1, swd1, wd1q1, wd1q2, H1D, H0D);
    wcolmax_k<<<dim3(DIN / 256, 1, 1), 256>>>(W_out, swo, H0D, DIN);
    wquant_k<<<dim3(DIN / 32, H0D / 32, 1), dim3(32, 8)>>>(W_out, swo, woq1, woq2, H0D, DIN);

    // 3. enc0 (grouped int8): h0 = relu(x @ W_enc0[c] + b) -> fp32
    tc_s8_k<true, true><<<dim3(H0D / S8_BN, BSZ / S8_BM, NC), S8_THREADS, S8_SMEM_TOTAL>>>(
        xq1, xq2, sx, w0q1, w0q2, sw0, b_enc0, h0f, BSZ, H0D, DIN);
    rowquant_k<<<BSZ, 256>>>(h0f, aq1, aq2, sa, H0D);

    // 4. enc1 (int8): h1 = relu(h0 @ W_enc1 + b)
    tc_s8_k<true, false><<<dim3(H1D / S8_BN, BSZ / S8_BM, 1), S8_THREADS, S8_SMEM_TOTAL>>>(
        aq1, aq2, sa, w1q1, w1q2, sw1, b_enc1, h1p, BSZ, H1D, H0D);

    // 5. heads (SIMT fp32, straight into d_out)
    gemm_k<false><<<dim3(LATD / BN, BSZ / BM), NTHREADS>>>(h1p, W_mu, b_mu, mu, LATD, H1D);
    gemm_k<false><<<dim3(LATD / BN, BSZ / BM), NTHREADS>>>(h1p, W_logvar, b_logvar, logvar, LATD, H1D);

    // 6. reparameterize
    z_k<<<(BSZ * LATD) / 256, 256>>>(mu, logvar, eps, zp, BSZ * LATD);

    // 7. dec0 (SIMT fp32, K=128): d0 = relu(z @ W_dec0 + b) -> reuse g_h1
    gemm_k<true><<<dim3(H1D / BN, BSZ / BM), NTHREADS>>>(zp, W_dec0, b_dec0, h1p, H1D, LATD);
    rowquant_k<<<BSZ, 256>>>(h1p, dq1, dq2, sd, H1D);

    // 8. dec1 (grouped int8): d1 = relu(d0 @ W_dec1[c] + b) -> reuse h0f
    tc_s8_k<true, true><<<dim3(H0D / S8_BN, BSZ / S8_BM, NC), S8_THREADS, S8_SMEM_TOTAL>>>(
        dq1, dq2, sd, wd1q1, wd1q2, swd1, b_dec1, h0f, BSZ, H0D, H1D);
    rowquant_k<<<BSZ, 256>>>(h0f, aq1, aq2, sa, H0D);

    // 9. out (int8): recon = d1 @ W_out + b
    tc_s8_k<false, false><<<dim3(DIN / S8_BN, BSZ / S8_BM, 1), S8_THREADS, S8_SMEM_TOTAL>>>(
        aq1, aq2, sa, woq1, woq2, swo, b_out, recon, BSZ, DIN, H0D);
}

// round 11
// speedup vs baseline: 2.7932x; 2.7932x over previous
#include <cuda_runtime.h>
#include <cuda_bf16.h>
#include <cstdint>
#include <math.h>

// ---------------------------------------------------------------------------
// Problem constants
// ---------------------------------------------------------------------------
#define BSZ   8192
#define DIN   2048
#define H0D   1024
#define H1D   512
#define LATD  128
#define NC    8

typedef __nv_bfloat16 bf16;

// ---------------------------------------------------------------------------
// Scratch (device globals)
// ---------------------------------------------------------------------------
__device__ bf16 g_xh [(size_t)BSZ * DIN];
__device__ bf16 g_xl [(size_t)BSZ * DIN];
__device__ bf16 g_w0h[(size_t)NC * H0D * DIN];   // enc0^T [C, H0, DIN]
__device__ bf16 g_w0l[(size_t)NC * H0D * DIN];
__device__ bf16 g_w1h[(size_t)H1D * H0D];        // enc1^T [H1, H0]
__device__ bf16 g_w1l[(size_t)H1D * H0D];
__device__ bf16 g_wmuh[(size_t)LATD * H1D];      // mu^T [LAT, H1]
__device__ bf16 g_wmul[(size_t)LATD * H1D];
__device__ bf16 g_wlvh[(size_t)LATD * H1D];      // logvar^T
__device__ bf16 g_wlvl[(size_t)LATD * H1D];
__device__ bf16 g_wd0h[(size_t)H1D * LATD];      // dec0^T [H1, LAT]
__device__ bf16 g_wd0l[(size_t)H1D * LATD];
__device__ bf16 g_wd1h[(size_t)NC * H0D * H1D];  // dec1^T [C, H0, H1]
__device__ bf16 g_wd1l[(size_t)NC * H0D * H1D];
__device__ bf16 g_woh[(size_t)DIN * H0D];        // out^T [DIN, H0]
__device__ bf16 g_wol[(size_t)DIN * H0D];
__device__ bf16 g_h0h[(size_t)BSZ * H0D];        // h0, reused as d1
__device__ bf16 g_h0l[(size_t)BSZ * H0D];
__device__ bf16 g_d0h[(size_t)BSZ * H1D];        // h1, reused as d0
__device__ bf16 g_d0l[(size_t)BSZ * H1D];
__device__ bf16 g_zh [(size_t)BSZ * LATD];
__device__ bf16 g_zl [(size_t)BSZ * LATD];
__device__ int   g_perm[NC * BSZ];
__device__ int   g_counts[NC];

// ---------------------------------------------------------------------------
// Routing
// ---------------------------------------------------------------------------
__global__ void reset_counts_k() {
    if (threadIdx.x < NC) g_counts[threadIdx.x] = 0;
}
__global__ void scatter_k(const int* __restrict__ labels) {
    int b = blockIdx.x * blockDim.x + threadIdx.x;
    if (b < BSZ) {
        int c = labels[b];
        int p = atomicAdd(&g_counts[c], 1);
        g_perm[c * BSZ + p] = b;
    }
}

// ---------------------------------------------------------------------------
// fp32 -> bf16 hi/lo split
// ---------------------------------------------------------------------------
__device__ __forceinline__ void split_bf16(float v, bf16& h, bf16& l) {
    h = __float2bfloat16_rn(v);
    l = __float2bfloat16_rn(v - __bfloat162float(h));
}

__global__ void convert_act_k(const float* __restrict__ X,
                              bf16* __restrict__ H, bf16* __restrict__ L, int n4) {
    int i = blockIdx.x * blockDim.x + threadIdx.x;
    if (i >= n4) return;
    float4 v = reinterpret_cast<const float4*>(X)[i];
    bf16 h0, h1, h2, h3, l0, l1, l2, l3;
    split_bf16(v.x, h0, l0); split_bf16(v.y, h1, l1);
    split_bf16(v.z, h2, l2); split_bf16(v.w, h3, l3);
    __nv_bfloat162 ph0 = __halves2bfloat162(h0, h1);
    __nv_bfloat162 ph1 = __halves2bfloat162(h2, h3);
    __nv_bfloat162 pl0 = __halves2bfloat162(l0, l1);
    __nv_bfloat162 pl1 = __halves2bfloat162(l2, l3);
    uint2 uh = make_uint2(*(uint32_t*)&ph0, *(uint32_t*)&ph1);
    uint2 ul = make_uint2(*(uint32_t*)&pl0, *(uint32_t*)&pl1);
    *reinterpret_cast<uint2*>(H + (size_t)i * 4) = uh;
    *reinterpret_cast<uint2*>(L + (size_t)i * 4) = ul;
}

// Weight convert + transpose: W [K,N] fp32 -> Th/Tl [N,K] bf16. grid.z = group.
__global__ void convert_wt_k(const float* __restrict__ W,
                             bf16* __restrict__ Th, bf16* __restrict__ Tl,
                             int K, int N) {
    __shared__ float tile[32][33];
    int g = blockIdx.z;
    const float* Wg = W + (size_t)g * K * N;
    bf16* Thg = Th + (size_t)g * N * K;
    bf16* Tlg = Tl + (size_t)g * N * K;
    int n0 = blockIdx.x * 32, k0 = blockIdx.y * 32;
    int tx = threadIdx.x, ty = threadIdx.y;   // 32 x 8
    #pragma unroll
    for (int i = 0; i < 4; i++)
        tile[ty + 8 * i][tx] = Wg[(size_t)(k0 + ty + 8 * i) * N + n0 + tx];
    __syncthreads();
    #pragma unroll
    for (int i = 0; i < 4; i++) {
        float v = tile[tx][ty + 8 * i];
        bf16 h, l;
        split_bf16(v, h, l);
        size_t o = (size_t)(n0 + ty + 8 * i) * K + k0 + tx;
        Thg[o] = h;
        Tlg[o] = l;
    }
}

// ---------------------------------------------------------------------------
// PTX wrappers
// ---------------------------------------------------------------------------
__device__ __forceinline__ uint32_t smem_u32(const void* p) {
    uint32_t a;
    asm("{ .reg .u64 t; cvta.to.shared.u64 t, %1; cvt.u32.u64 %0, t; }"
        : "=r"(a) : "l"(p));
    return a;
}

__device__ __forceinline__ void cp_async16(uint32_t saddr, const void* g, bool ok) {
    int sz = ok ? 16 : 0;
    asm volatile("cp.async.cg.shared.global [%0], [%1], 16, %2;"
                 :: "r"(saddr), "l"(g), "r"(sz));
}
#define CP_COMMIT() asm volatile("cp.async.commit_group;" ::: "memory")
#define CP_WAIT(n)  asm volatile("cp.async.wait_group %0;" :: "n"(n) : "memory")

__device__ __forceinline__ void ldsm_x4(uint32_t* r, uint32_t addr) {
    asm volatile("ldmatrix.sync.aligned.m8n8.x4.shared.b16 {%0,%1,%2,%3}, [%4];"
                 : "=r"(r[0]), "=r"(r[1]), "=r"(r[2]), "=r"(r[3]) : "r"(addr));
}

__device__ __forceinline__ void mma16816(float* c, const uint32_t* a, const uint32_t* b) {
    asm volatile(
        "mma.sync.aligned.m16n8k16.row.col.f32.bf16.bf16.f32 "
        "{%0,%1,%2,%3}, {%4,%5,%6,%7}, {%8,%9}, {%0,%1,%2,%3};"
        : "+f"(c[0]), "+f"(c[1]), "+f"(c[2]), "+f"(c[3])
        : "r"(a[0]), "r"(a[1]), "r"(a[2]), "r"(a[3]), "r"(b[0]), "r"(b[1]));
}

// ---------------------------------------------------------------------------
// mma.sync GEMM: 256x128x32 CTA tile, bf16x3 split, 3-stage cp.async pipeline.
// smem rows: 32 bf16 = 64B tight, XOR chunk swizzle c' = v ^ ((row>>1)&3).
// MMA passes hh / hl / lh are fully separated (16 independent accumulators
// per pass, no adjacent same-accumulator RAW pairs).
// ---------------------------------------------------------------------------
#define TC_BM 256
#define TC_BN 128
#define TC_KC 32
#define TC_THREADS 512
#define TC_NSTAGE 3

#define A_TILE_B (TC_BM * 64)
#define B_TILE_B (TC_BN * 64)
#define STAGE_B  (2 * A_TILE_B + 2 * B_TILE_B)
#define OFF_AH 0
#define OFF_AL A_TILE_B
#define OFF_BH (2 * A_TILE_B)
#define OFF_BL (2 * A_TILE_B + B_TILE_B)
#define SM_ROWS_OFF (TC_NSTAGE * STAGE_B)
#define TC_SMEM_TOTAL (SM_ROWS_OFF + TC_BM * 4)

__device__ __forceinline__ uint32_t swz_off(int row, int v) {
    return (uint32_t)(row * 64 + ((v ^ ((row >> 1) & 3)) << 4));
}

template <bool GROUPED>
__device__ __forceinline__ void tc_load_stage(
    uint32_t stage_base, const int* __restrict__ rows, int tid, int k0,
    const bf16* __restrict__ Ah, const bf16* __restrict__ Al,
    const bf16* __restrict__ Bh, const bf16* __restrict__ Bl,
    int m0, int n0, int K)
{
    #pragma unroll
    for (int t = 0; t < 6; t++) {
        int idx = tid + t * TC_THREADS;
        if (idx < 2048) {
            int tile = idx >> 10;
            int rem  = idx & 1023;
            int row  = rem >> 2;
            int v    = rem & 3;
            int gr = GROUPED ? rows[row] : (m0 + row);
            bool ok = !GROUPED || (gr >= 0);
            const bf16* src = tile ? Al : Ah;
            cp_async16(stage_base + (tile ? OFF_AL : OFF_AH) + swz_off(row, v),
                       src + ((size_t)(ok ? gr : 0) * K + k0 + v * 8), ok);
        } else {
            int j    = idx - 2048;
            int tile = j >> 9;
            int rem  = j & 511;
            int row  = rem >> 2;
            int v    = rem & 3;
            const bf16* src = tile ? Bl : Bh;
            cp_async16(stage_base + (tile ? OFF_BL : OFF_BH) + swz_off(row, v),
                       src + ((size_t)(n0 + row) * K + k0 + v * 8), true);
        }
    }
}

// OUTMODE: 0 = fp32 Out, 1 = bf16 hi/lo Oh/Ol
template <bool RELU, bool GROUPED, int OUTMODE>
__global__ void __launch_bounds__(TC_THREADS, 1)
tc_gemm_k(const bf16* __restrict__ Ah, const bf16* __restrict__ Al,
          const bf16* __restrict__ Bhg, const bf16* __restrict__ Blg,
          const float* __restrict__ biasg,
          float* __restrict__ OutF,
          bf16* __restrict__ Oh, bf16* __restrict__ Ol,
          int M, int N, int K)
{
    extern __shared__ char smem[];
    const int tid  = threadIdx.x;
    const int wid  = tid >> 5;
    const int lane = tid & 31;
    const int wm   = wid >> 2;   // 0..3 (64-row band)
    const int wn   = wid & 3;    // 0..3 (32-col band)
    const int g    = GROUPED ? blockIdx.z : 0;
    const int m0   = blockIdx.y * TC_BM;
    if (GROUPED) {
        if (m0 >= g_counts[g]) return;
    }
    const int n0 = blockIdx.x * TC_BN;
    uint32_t sb = smem_u32(smem);
    int* rows_s = reinterpret_cast<int*>(smem + SM_ROWS_OFF);

    if (GROUPED) {
        if (tid < TC_BM) {
            int cnt = g_counts[g];
            int r = m0 + tid;
            rows_s[tid] = (r < cnt) ? g_perm[g * BSZ + r] : -1;
        }
        __syncthreads();
    }

    const bf16* Bh = Bhg + (GROUPED ? (size_t)g * N * K : 0);
    const bf16* Bl = Blg + (GROUPED ? (size_t)g * N * K : 0);

    float acc[4][4][4];
    #pragma unroll
    for (int i = 0; i < 4; i++)
        #pragma unroll
        for (int j = 0; j < 4; j++)
            #pragma unroll
            for (int q = 0; q < 4; q++) acc[i][j][q] = 0.f;

    const int nchunks = K / TC_KC;

    tc_load_stage<GROUPED>(sb + 0 * STAGE_B, rows_s, tid, 0, Ah, Al, Bh, Bl, m0, n0, K);
    CP_COMMIT();
    tc_load_stage<GROUPED>(sb + 1 * STAGE_B, rows_s, tid, TC_KC, Ah, Al, Bh, Bl, m0, n0, K);
    CP_COMMIT();

    int stage = 0;
    for (int i = 0; i < nchunks; i++) {
        if (i + 1 < nchunks) { CP_WAIT(1); } else { CP_WAIT(0); }
        __syncthreads();

        if (i + 2 < nchunks) {
            int ps = stage + 2; if (ps >= TC_NSTAGE) ps -= TC_NSTAGE;
            tc_load_stage<GROUPED>(sb + ps * STAGE_B, rows_s, tid, (i + 2) * TC_KC,
                                   Ah, Al, Bh, Bl, m0, n0, K);
            CP_COMMIT();
        }

        uint32_t st = sb + stage * STAGE_B;
        #pragma unroll
        for (int kk = 0; kk < 2; kk++) {
            const int vb = kk * 2 + (lane >> 4);
            // B fragments
            uint32_t bh[8], bl[8];
            #pragma unroll
            for (int p = 0; p < 2; p++) {
                int brow = wn * 32 + p * 16 + (lane & 15);
                uint32_t r[4];
                ldsm_x4(r, st + OFF_BH + swz_off(brow, vb));
                bh[4 * p + 0] = r[0]; bh[4 * p + 1] = r[2];
                bh[4 * p + 2] = r[1]; bh[4 * p + 3] = r[3];
                ldsm_x4(r, st + OFF_BL + swz_off(brow, vb));
                bl[4 * p + 0] = r[0]; bl[4 * p + 1] = r[2];
                bl[4 * p + 2] = r[1]; bl[4 * p + 3] = r[3];
            }
            // A hi fragments
            uint32_t a[4][4];
            #pragma unroll
            for (int mt = 0; mt < 4; mt++) {
                int arow = wm * 64 + mt * 16 + (lane & 15);
                ldsm_x4(a[mt], st + OFF_AH + swz_off(arow, vb));
            }
            // pass hh (16 independent accs)
            #pragma unroll
            for (int mt = 0; mt < 4; mt++)
                #pragma unroll
                for (int nt = 0; nt < 4; nt++)
                    mma16816(acc[mt][nt], a[mt], &bh[2 * nt]);
            // pass hl (16 independent accs)
            #pragma unroll
            for (int mt = 0; mt < 4; mt++)
                #pragma unroll
                for (int nt = 0; nt < 4; nt++)
                    mma16816(acc[mt][nt], a[mt], &bl[2 * nt]);
            // A lo fragments (overwrite)
            #pragma unroll
            for (int mt = 0; mt < 4; mt++) {
                int arow = wm * 64 + mt * 16 + (lane & 15);
                ldsm_x4(a[mt], st + OFF_AL + swz_off(arow, vb));
            }
            // pass lh
            #pragma unroll
            for (int mt = 0; mt < 4; mt++)
                #pragma unroll
                for (int nt = 0; nt < 4; nt++)
                    mma16816(acc[mt][nt], a[mt], &bh[2 * nt]);
        }
        stage = stage + 1; if (stage >= TC_NSTAGE) stage = 0;
    }

    // Epilogue
    const float* bias = biasg + (GROUPED ? (size_t)g * N : 0);
    #pragma unroll
    for (int mt = 0; mt < 4; mt++) {
        #pragma unroll
        for (int half = 0; half < 2; half++) {
            int rloc = wm * 64 + mt * 16 + (lane >> 2) + half * 8;
            int gm = GROUPED ? rows_s[rloc] : (m0 + rloc);
            if (GROUPED && gm < 0) continue;
            #pragma unroll
            for (int nt = 0; nt < 4; nt++) {
                int col = n0 + wn * 32 + nt * 8 + 2 * (lane & 3);
                float c0 = acc[mt][nt][2 * half + 0] + bias[col];
                float c1 = acc[mt][nt][2 * half + 1] + bias[col + 1];
                if (RELU) { c0 = fmaxf(c0, 0.f); c1 = fmaxf(c1, 0.f); }
                if (OUTMODE == 0) {
                    *reinterpret_cast<float2*>(OutF + (size_t)gm * N + col) =
                        make_float2(c0, c1);
                } else {
                    bf16 h0, h1, l0, l1;
                    split_bf16(c0, h0, l0);
                    split_bf16(c1, h1, l1);
                    __nv_bfloat162 ph = __halves2bfloat162(h0, h1);
                    __nv_bfloat162 pl = __halves2bfloat162(l0, l1);
                    *reinterpret_cast<uint32_t*>(Oh + (size_t)gm * N + col) =
                        *reinterpret_cast<uint32_t*>(&ph);
                    *reinterpret_cast<uint32_t*>(Ol + (size_t)gm * N + col) =
                        *reinterpret_cast<uint32_t*>(&pl);
                }
            }
        }
    }
}

// ---------------------------------------------------------------------------
// Reparameterize + hi/lo split: z = mu + eps * exp(0.5 * logvar)
// ---------------------------------------------------------------------------
__global__ void z_k(const float* __restrict__ mu, const float* __restrict__ logvar,
                    const float* __restrict__ eps,
                    bf16* __restrict__ Zh, bf16* __restrict__ Zl, int n2) {
    int i = blockIdx.x * blockDim.x + threadIdx.x;
    if (i >= n2) return;
    float2 m  = reinterpret_cast<const float2*>(mu)[i];
    float2 lv = reinterpret_cast<const float2*>(logvar)[i];
    float2 e  = reinterpret_cast<const float2*>(eps)[i];
    float z0 = fmaf(e.x, expf(0.5f * lv.x), m.x);
    float z1 = fmaf(e.y, expf(0.5f * lv.y), m.y);
    bf16 h0, h1, l0, l1;
    split_bf16(z0, h0, l0);
    split_bf16(z1, h1, l1);
    __nv_bfloat162 ph = __halves2bfloat162(h0, h1);
    __nv_bfloat162 pl = __halves2bfloat162(l0, l1);
    reinterpret_cast<uint32_t*>(Zh)[i] = *reinterpret_cast<uint32_t*>(&ph);
    reinterpret_cast<uint32_t*>(Zl)[i] = *reinterpret_cast<uint32_t*>(&pl);
}

// ---------------------------------------------------------------------------
// Launcher
// ---------------------------------------------------------------------------
extern "C" void kernel_launch(void* const* d_in, const int* in_sizes, int n_in,
                              void* d_out, int out_size) {
    const float* x        = (const float*)d_in[0];
    const int*   labels   = (const int*)  d_in[1];
    const float* eps      = (const float*)d_in[2];
    const float* W_enc0   = (const float*)d_in[3];
    const float* b_enc0   = (const float*)d_in[4];
    const float* W_enc1   = (const float*)d_in[5];
    const float* b_enc1   = (const float*)d_in[6];
    const float* W_mu     = (const float*)d_in[7];
    const float* b_mu     = (const float*)d_in[8];
    const float* W_logvar = (const float*)d_in[9];
    const float* b_logvar = (const float*)d_in[10];
    const float* W_dec0   = (const float*)d_in[11];
    const float* b_dec0   = (const float*)d_in[12];
    const float* W_dec1   = (const float*)d_in[13];
    const float* b_dec1   = (const float*)d_in[14];
    const float* W_out    = (const float*)d_in[15];
    const float* b_out    = (const float*)d_in[16];

    float* recon  = (float*)d_out;
    float* mu     = recon + (size_t)BSZ * DIN;
    float* logvar = mu    + (size_t)BSZ * LATD;

    bf16 *xh, *xl, *w0h, *w0l, *w1h, *w1l, *wmuh, *wmul, *wlvh, *wlvl;
    bf16 *wd0h, *wd0l, *wd1h, *wd1l, *woh, *wol;
    bf16 *h0h, *h0l, *d0h, *d0l, *zh, *zl;
    cudaGetSymbolAddress((void**)&xh,  g_xh);   cudaGetSymbolAddress((void**)&xl,  g_xl);
    cudaGetSymbolAddress((void**)&w0h, g_w0h);  cudaGetSymbolAddress((void**)&w0l, g_w0l);
    cudaGetSymbolAddress((void**)&w1h, g_w1h);  cudaGetSymbolAddress((void**)&w1l, g_w1l);
    cudaGetSymbolAddress((void**)&wmuh, g_wmuh); cudaGetSymbolAddress((void**)&wmul, g_wmul);
    cudaGetSymbolAddress((void**)&wlvh, g_wlvh); cudaGetSymbolAddress((void**)&wlvl, g_wlvl);
    cudaGetSymbolAddress((void**)&wd0h, g_wd0h); cudaGetSymbolAddress((void**)&wd0l, g_wd0l);
    cudaGetSymbolAddress((void**)&wd1h, g_wd1h); cudaGetSymbolAddress((void**)&wd1l, g_wd1l);
    cudaGetSymbolAddress((void**)&woh, g_woh);  cudaGetSymbolAddress((void**)&wol, g_wol);
    cudaGetSymbolAddress((void**)&h0h, g_h0h);  cudaGetSymbolAddress((void**)&h0l, g_h0l);
    cudaGetSymbolAddress((void**)&d0h, g_d0h);  cudaGetSymbolAddress((void**)&d0l, g_d0l);
    cudaGetSymbolAddress((void**)&zh,  g_zh);   cudaGetSymbolAddress((void**)&zl,  g_zl);

    cudaFuncSetAttribute(tc_gemm_k<true,  true,  1>,
                         cudaFuncAttributeMaxDynamicSharedMemorySize, TC_SMEM_TOTAL);
    cudaFuncSetAttribute(tc_gemm_k<true,  false, 1>,
                         cudaFuncAttributeMaxDynamicSharedMemorySize, TC_SMEM_TOTAL);
    cudaFuncSetAttribute(tc_gemm_k<false, false, 0>,
                         cudaFuncAttributeMaxDynamicSharedMemorySize, TC_SMEM_TOTAL);

    // 1. routing
    reset_counts_k<<<1, 32>>>();
    scatter_k<<<BSZ / 256, 256>>>(labels);

    // 2. conversions (hi/lo bf16, weights transposed to [N,K])
    convert_act_k<<<(BSZ * DIN / 4) / 256, 256>>>(x, xh, xl, BSZ * DIN / 4);
    convert_wt_k<<<dim3(H0D / 32, DIN / 32, NC), dim3(32, 8)>>>(W_enc0, w0h, w0l, DIN, H0D);
    convert_wt_k<<<dim3(H1D / 32, H0D / 32, 1), dim3(32, 8)>>>(W_enc1, w1h, w1l, H0D, H1D);
    convert_wt_k<<<dim3(LATD / 32, H1D / 32, 1), dim3(32, 8)>>>(W_mu, wmuh, wmul, H1D, LATD);
    convert_wt_k<<<dim3(LATD / 32, H1D / 32, 1), dim3(32, 8)>>>(W_logvar, wlvh, wlvl, H1D, LATD);
    convert_wt_k<<<dim3(H1D / 32, LATD / 32, 1), dim3(32, 8)>>>(W_dec0, wd0h, wd0l, LATD, H1D);
    convert_wt_k<<<dim3(H0D / 32, H1D / 32, NC), dim3(32, 8)>>>(W_dec1, wd1h, wd1l, H1D, H0D);
    convert_wt_k<<<dim3(DIN / 32, H0D / 32, 1), dim3(32, 8)>>>(W_out, woh, wol, H0D, DIN);

    // 3. enc0 (grouped): h0 = relu(x @ W_enc0[c] + b) -> bf16 hi/lo
    tc_gemm_k<true, true, 1><<<dim3(H0D / TC_BN, BSZ / TC_BM, NC), TC_THREADS, TC_SMEM_TOTAL>>>(
        xh, xl, w0h, w0l, b_enc0, nullptr, h0h, h0l, BSZ, H0D, DIN);

    // 4. enc1: h1 = relu(h0 @ W_enc1 + b) -> bf16 hi/lo (into d0 buffers)
    tc_gemm_k<true, false, 1><<<dim3(H1D / TC_BN, BSZ / TC_BM, 1), TC_THREADS, TC_SMEM_TOTAL>>>(
        h0h, h0l, w1h, w1l, b_enc1, nullptr, d0h, d0l, BSZ, H1D, H0D);

    // 5. heads: mu / logvar (tc, fp32 straight into d_out)
    tc_gemm_k<false, false, 0><<<dim3(LATD / TC_BN, BSZ / TC_BM, 1), TC_THREADS, TC_SMEM_TOTAL>>>(
        d0h, d0l, wmuh, wmul, b_mu, mu, nullptr, nullptr, BSZ, LATD, H1D);
    tc_gemm_k<false, false, 0><<<dim3(LATD / TC_BN, BSZ / TC_BM, 1), TC_THREADS, TC_SMEM_TOTAL>>>(
        d0h, d0l, wlvh, wlvl, b_logvar, logvar, nullptr, nullptr, BSZ, LATD, H1D);

    // 6. reparameterize -> z hi/lo
    z_k<<<(BSZ * LATD / 2) / 256, 256>>>(mu, logvar, eps, zh, zl, BSZ * LATD / 2);

    // 7. dec0: d0 = relu(z @ W_dec0 + b) -> bf16 hi/lo (reuse d0 buffers; h1 dead)
    tc_gemm_k<true, false, 1><<<dim3(H1D / TC_BN, BSZ / TC_BM, 1), TC_THREADS, TC_SMEM_TOTAL>>>(
        zh, zl, wd0h, wd0l, b_dec0, nullptr, d0h, d0l, BSZ, H1D, LATD);

    // 8. dec1 (grouped): d1 = relu(d0 @ W_dec1[c] + b) -> bf16 hi/lo (reuse h0 bufs)
    tc_gemm_k<true, true, 1><<<dim3(H0D / TC_BN, BSZ / TC_BM, NC), TC_THREADS, TC_SMEM_TOTAL>>>(
        d0h, d0l, wd1h, wd1l, b_dec1, nullptr, h0h, h0l, BSZ, H0D, H1D);

    // 9. out: recon = d1 @ W_out + b -> fp32
    tc_gemm_k<false, false, 0><<<dim3(DIN / TC_BN, BSZ / TC_BM, 1), TC_THREADS, TC_SMEM_TOTAL>>>(
        h0h, h0l, woh, wol, b_out, recon, nullptr, nullptr, BSZ, DIN, H0D);
}